// round 16
// baseline (speedup 1.0000x reference)
#include <cuda_runtime.h>
#include <stdint.h>

// GazeOnce360 post-processing, round 16: TWO kernels, register-split right.
//   K1 scan: LOW-REG (PF=4) pure conf scan -> per-bin buckets. 512 blocks all
//       resident in one wave -> warp-level latency hiding for the MLP-bound scan.
//   K2 tail (16 blocks): block 15 = finish (suffix-scan -> cutoff -> atomic-free
//       gather -> rank sort -> decode) -> flag; blocks 0-14 spin then mask
//       chunks; last-done block = 16-step word-sweep NMS + output + resets.

#define KDET 512
#define NBINS 8192
#define BIN_BASE (0x3F666667u >> 8)   // bits of smallest float > 0.9f, >>8
#define SLOTS 128                     // per-bin capacity
#define CAND_CAP 1024
#define PF 4                          // float4 loads per thread in scan (low regs)

__device__ unsigned int       g_hist[NBINS];          // slot counters (==hist)
__device__ unsigned long long g_bins[NBINS * SLOTS];  // bucket store
__device__ float4             g_cand[KDET];
__device__ float              g_score[KDET];
__device__ unsigned int       g_sup[16 * KDET];       // [word w][row r]
__device__ unsigned int       g_flag, g_done2;

// =================== K1: scan -> buckets (low-register) ===================
// softmax(c0,c1)[1] == 1/(exp(c0-c1)+1) when c1>c0 (e1=1 form); __expf/
// __fdividef err ~1e-7 << ~1.4e-5 adjacent-rank gap at the top-512 boundary.
// Prefilter d>2.19 (< ln9; sigmoid(2.19)=0.8993): zero-padded tails fail it.
__global__ void __launch_bounds__(512) k_scan(const float4* __restrict__ conf4,
                                              int nPairs) {
    int t = threadIdx.x;
    int base = blockIdx.x * (512 * PF) + t;
    bool full = (blockIdx.x + 1) * (512 * PF) <= nPairs;   // block-uniform
    float4 f[PF];
    if (full) {
#pragma unroll
        for (int k = 0; k < PF; k++) f[k] = conf4[base + k * 512];
    } else {
#pragma unroll
        for (int k = 0; k < PF; k++) {
            int idx = base + k * 512;
            f[k] = (idx < nPairs) ? conf4[idx] : make_float4(0.f, 0.f, 0.f, 0.f);
        }
    }
#pragma unroll
    for (int k = 0; k < PF; k++) {
#pragma unroll
        for (int q = 0; q < 2; q++) {
            float c0 = q ? f[k].z : f[k].x;
            float c1 = q ? f[k].w : f[k].y;
            if (c1 - c0 > 2.19f) {
                float e0 = __expf(c0 - c1);
                float s  = __fdividef(1.0f, e0 + 1.0f);
                if (s > 0.9f) {
                    unsigned bits = __float_as_uint(s);
                    unsigned bin  = (bits >> 8) - BIN_BASE;
                    unsigned slot = atomicAdd(&g_hist[bin], 1u);
                    if (slot < SLOTS) {
                        unsigned ei = 2u * (unsigned)(base + k * 512) + (unsigned)q;
                        g_bins[bin * SLOTS + slot] =
                            ((unsigned long long)bits << 32)
                          | (unsigned long long)(0xFFFFFFFFu - ei);
                    }
                }
            }
        }
    }
}

// =================== K2: tail pipeline (16 blocks) ===================
__global__ void __launch_bounds__(512) k_tail(const float4* __restrict__ loc4,
                                              const float4* __restrict__ pri4,
                                              float* __restrict__ out) {
    int t = threadIdx.x;
    int b = blockIdx.x;                               // 0..15

    __shared__ float4 scand[KDET];
    __shared__ float  sa04[KDET];                     // 0.4f * area
    float4 bi; float sc;

    if (b == 15) {
        // ---------------- finish: select + gather + sort + decode -----------
        __shared__ unsigned sB, wtot[16];
        __shared__ unsigned long long sk[CAND_CAP];
        __shared__ unsigned long long sk2[CAND_CAP];
        __shared__ unsigned sinfo[CAND_CAP];
        if (t == 0) sB = 0u;
        sk[t] = 0ULL;  sk[t + 512] = 0ULL;
        sk2[t] = 0ULL; sk2[t + 512] = 0ULL;
        sinfo[t] = 0u; sinfo[t + 512] = 0u;

        // load 16 bins as 4x uint4
        unsigned h[16];
        {
            const uint4* hv = (const uint4*)&g_hist[t * 16];
            uint4 a = hv[0], bb = hv[1], cc = hv[2], d = hv[3];
            h[0]=a.x; h[1]=a.y; h[2]=a.z; h[3]=a.w;
            h[4]=bb.x; h[5]=bb.y; h[6]=bb.z; h[7]=bb.w;
            h[8]=cc.x; h[9]=cc.y; h[10]=cc.z; h[11]=cc.w;
            h[12]=d.x; h[13]=d.y; h[14]=d.z; h[15]=d.w;
        }
        unsigned psum = 0;
#pragma unroll
        for (int j = 0; j < 16; j++) psum += h[j];

        // suffix-inclusive scan over 512 threads: warp shuffle + smem tail
        unsigned s = psum;
        int lane = t & 31, wid = t >> 5;
#pragma unroll
        for (int off = 1; off < 32; off <<= 1) {
            unsigned v = __shfl_down_sync(0xFFFFFFFFu, s, off);
            if (lane + off < 32) s += v;
        }
        if (lane == 0) wtot[wid] = s;
        __syncthreads();
        unsigned tail = 0;
        for (int w2 = wid + 1; w2 < 16; w2++) tail += wtot[w2];
        unsigned suf_excl = s + tail - psum;          // sum of bins >= 16(t+1)

        // B = max bin with suffix-count >= 512 (else 0)
        {
            unsigned cum = suf_excl;
            int best = -1;
#pragma unroll
            for (int j = 15; j >= 0; j--) {
                cum += h[j];
                if (cum >= KDET) { best = t * 16 + j; break; }
            }
            if (best >= 0) atomicMax(&sB, (unsigned)best);
        }
        __syncthreads();
        unsigned B = sB;

        // ATOMIC-FREE direct gather (exact bases from suffix scan)
        {
            unsigned suf = suf_excl;
#pragma unroll
            for (int j = 15; j >= 0; j--) {
                unsigned bb = (unsigned)t * 16 + (unsigned)j;
                if (bb >= B && h[j] > 0 && suf < CAND_CAP) {
                    unsigned cn = min(min(h[j], (unsigned)SLOTS),
                                      (unsigned)CAND_CAP - suf);
                    unsigned info = (suf << 16) | cn;
                    for (unsigned k = 0; k < cn; k++) {
                        sk[suf + k] = g_bins[bb * SLOTS + k];
                        sinfo[suf + k] = info;
                    }
                }
                suf += h[j];
            }
        }
        __syncthreads();

        // intra-bin rank sort
#pragma unroll
        for (int r = 0; r < 2; r++) {
            int p = t + r * 512;
            unsigned long long key = sk[p];
            if (key) {
                unsigned info = sinfo[p];
                unsigned bs = info >> 16, cn = info & 0xFFFFu;
                unsigned rank2 = 0;
                for (unsigned k = 0; k < cn; k++)
                    rank2 += (sk[bs + k] > key) ? 1u : 0u;
                sk2[bs + rank2] = key;
            }
        }
        __syncthreads();

        // decode top 512
        {
            unsigned long long key = sk2[t];
            unsigned sb = (unsigned)(key >> 32);
            float4 c = make_float4(0.f, 0.f, 0.f, 0.f);
            sc = 0.f;
            if (sb) {
                unsigned idx = 0xFFFFFFFFu - (unsigned)(key & 0xFFFFFFFFull);
                float4 l = loc4[idx];
                float4 p = pri4[idx];
                float cx = p.x + (l.x * 0.1f) * p.z;
                float cy = p.y + (l.y * 0.1f) * p.w;
                float w  = p.z * expf(l.z * 0.2f);
                float hh = p.w * expf(l.w * 0.2f);
                float x1 = cx - w * 0.5f;
                float y1 = cy - hh * 0.5f;
                float x2 = x1 + w;
                float y2 = y1 + hh;
                c = make_float4(x1 * 2048.f, y1 * 2048.f, x2 * 2048.f, y2 * 2048.f);
                sc = __uint_as_float(sb);
            }
            g_cand[t]  = c;
            g_score[t] = sc;
            bi = c;
            scand[t] = c;
            sa04[t]  = 0.4f * (c.z - c.x + 1.f) * (c.w - c.y + 1.f);
        }
        __threadfence();
        __syncthreads();
        if (t == 0) atomicExch(&g_flag, 1u);          // release decode
    } else {
        // spinner: wait for decode (all 16 blocks resident by construction)
        if (t == 0) {
            while (atomicAdd(&g_flag, 0u) == 0u) __nanosleep(64);
        }
        __syncthreads();
        __threadfence();                              // acquire
        bi = g_cand[t];
        sc = g_score[t];
        scand[t] = bi;
        sa04[t]  = 0.4f * (bi.z - bi.x + 1.f) * (bi.w - bi.y + 1.f);
    }
    __syncthreads();

    // ---------------- mask chunk (division-free IoU) ----------------
    // iou>0.4 <=> 1.4*inter > 0.4*(areai+areaj)  (areas >= 1 so denom > 0)
    {
        float a04 = sa04[t];
        unsigned bits = 0u;
#pragma unroll 8
        for (int bb = 0; bb < 32; bb++) {
            int j = b * 32 + bb;
            float4 bj = scand[j];
            float xx1 = fmaxf(bi.x, bj.x), yy1 = fmaxf(bi.y, bj.y);
            float xx2 = fminf(bi.z, bj.z), yy2 = fminf(bi.w, bj.w);
            float ww = fmaxf(xx2 - xx1 + 1.f, 0.f);
            float hh = fmaxf(yy2 - yy1 + 1.f, 0.f);
            float inter = ww * hh;
            bool sgt = 1.4f * inter > a04 + sa04[j];
            if (sgt && j < t) bits |= (1u << bb);
        }
        g_sup[b * 512 + t] = bits;
    }

    // last-done election
    __shared__ unsigned s_last;
    __syncthreads();
    if (t == 0) {
        __threadfence();
        unsigned old = atomicAdd(&g_done2, 1u);
        s_last = (old == 15u) ? 1u : 0u;
    }
    __syncthreads();
    if (!s_last) return;
    __threadfence();

    // ---------------- forward word-sweep NMS (exact, 16 steps) -----------
    unsigned supw[16];
#pragma unroll
    for (int w = 0; w < 16; w++) supw[w] = g_sup[w * 512 + t];
    int wme = t >> 5, lane = t & 31;
    unsigned intra = g_sup[wme * 512 + t];
    bool k0 = sc > 0.0f;                              // keep0 = top_s > 0
    unsigned below = (1u << lane) - 1u;

    // restore scratch invariant for next replay (hist = 0)
    {
        uint4* hz = (uint4*)g_hist;
#pragma unroll
        for (int i = 0; i < 4; i++)
            hz[t + i * 512] = make_uint4(0u, 0u, 0u, 0u);
    }

    __shared__ unsigned skeep[16];
    bool suppressed = false;
#pragma unroll
    for (int w = 0; w < 16; w++) {
        if (wme == w) {
            // intra-word greedy via word-local Jacobi (exact; terminates <=33
            // by strict lower-index dependency; consecutive-equal pins it)
            unsigned tent = __ballot_sync(0xFFFFFFFFu, k0 && !suppressed);
            unsigned fcur = tent, prev;
            do {
                prev = fcur;
                bool killed = (intra & fcur & below) != 0u;
                fcur = __ballot_sync(0xFFFFFFFFu, !killed) & tent;
            } while (fcur != prev);
            if (lane == 0) skeep[w] = fcur;
        }
        __syncthreads();
        suppressed = suppressed || ((supw[w] & skeep[w]) != 0u);
    }

    unsigned kept = (skeep[wme] >> lane) & 1u;
    const float inv = 1.0f / 2048.0f;                 // exact (power of 2)
    float o0 = 0.f, o1 = 0.f, o2 = 0.f, o3 = 0.f, o4 = 0.f;
    if (kept) { o0 = bi.x * inv; o1 = bi.y * inv; o2 = bi.z * inv; o3 = bi.w * inv; o4 = sc; }
    out[t * 5 + 0] = o0;
    out[t * 5 + 1] = o1;
    out[t * 5 + 2] = o2;
    out[t * 5 + 3] = o3;
    out[t * 5 + 4] = o4;

    if (t == 0) { g_flag = 0u; g_done2 = 0u; }
}

extern "C" void kernel_launch(void* const* d_in, const int* in_sizes, int n_in,
                              void* d_out, int out_size) {
    const float4* loc4  = (const float4*)d_in[0];
    const float4* conf4 = (const float4*)d_in[1];
    const float4* pri4  = (const float4*)d_in[2];
    float* out = (float*)d_out;

    int nElem  = in_sizes[1] / 2;                   // N priors
    int nPairs = (nElem + 1) / 2;                   // float4 count of conf
    int G = (nPairs + 512 * PF - 1) / (512 * PF);   // 512 blocks for N=2M

    k_scan<<<G, 512>>>(conf4, nPairs);
    k_tail<<<16, 512>>>(loc4, pri4, out);
}

// round 17
// speedup vs baseline: 1.0513x; 1.0513x over previous
#include <cuda_runtime.h>
#include <stdint.h>

// GazeOnce360 post-processing, round 17: TWO kernels.
//   K1 scan: low-reg PF=4 conf scan -> per-bin buckets (fallback) AND a flat
//       fast array of keys with s > 0.992 (expected ~690 >= 512 -> the top-512
//       cutoff s~0.9927 lies inside it).
//   K2 tail (16 blocks): block 15 = finish. FAST PATH: coalesced-load the fast
//       array, full rank-sort (broadcast LDS scans), top-512 by global rank,
//       decode. FALLBACK (nf<512 or nf>2048): old hist suffix-scan/gather path.
//       Blocks 0-14 spin on flag then mask chunks; last-done block = word-sweep
//       NMS + output + scratch resets.

#define KDET 512
#define NBINS 8192
#define BIN_BASE (0x3F666667u >> 8)   // bits of smallest float > 0.9f, >>8
#define SLOTS 128                     // per-bin capacity
#define CAND_CAP 1024
#define FASTCAP 2048
#define PF 4                          // float4 loads per thread in scan

__device__ unsigned int       g_hist[NBINS];          // slot counters (==hist)
__device__ unsigned long long g_bins[NBINS * SLOTS];  // bucket store (fallback)
__device__ unsigned long long g_fast[FASTCAP];        // flat fast-key array
__device__ unsigned int       g_nfast;
__device__ float4             g_cand[KDET];
__device__ float              g_score[KDET];
__device__ unsigned int       g_sup[16 * KDET];       // [word w][row r]
__device__ unsigned int       g_flag, g_done2;

// =================== K1: scan ===================
// softmax(c0,c1)[1] == 1/(exp(c0-c1)+1) when c1>c0 (e1=1 form); __expf/
// __fdividef err ~1e-7 << ~1.4e-5 adjacent-rank gap at the top-512 boundary.
// Prefilter d>2.19 (< ln9; sigmoid(2.19)=0.8993): zero-padded tails fail it.
__global__ void __launch_bounds__(512) k_scan(const float4* __restrict__ conf4,
                                              int nPairs) {
    int t = threadIdx.x;
    int base = blockIdx.x * (512 * PF) + t;
    bool full = (blockIdx.x + 1) * (512 * PF) <= nPairs;   // block-uniform
    float4 f[PF];
    if (full) {
#pragma unroll
        for (int k = 0; k < PF; k++) f[k] = conf4[base + k * 512];
    } else {
#pragma unroll
        for (int k = 0; k < PF; k++) {
            int idx = base + k * 512;
            f[k] = (idx < nPairs) ? conf4[idx] : make_float4(0.f, 0.f, 0.f, 0.f);
        }
    }
#pragma unroll
    for (int k = 0; k < PF; k++) {
#pragma unroll
        for (int q = 0; q < 2; q++) {
            float c0 = q ? f[k].z : f[k].x;
            float c1 = q ? f[k].w : f[k].y;
            if (c1 - c0 > 2.19f) {
                float e0 = __expf(c0 - c1);
                float s  = __fdividef(1.0f, e0 + 1.0f);
                if (s > 0.9f) {
                    unsigned bits = __float_as_uint(s);
                    unsigned ei = 2u * (unsigned)(base + k * 512) + (unsigned)q;
                    unsigned long long key =
                        ((unsigned long long)bits << 32)
                      | (unsigned long long)(0xFFFFFFFFu - ei);
                    unsigned bin  = (bits >> 8) - BIN_BASE;
                    unsigned slot = atomicAdd(&g_hist[bin], 1u);
                    if (slot < SLOTS) g_bins[bin * SLOTS + slot] = key;
                    if (s > 0.992f) {                 // fast set (top-512 superset)
                        unsigned fp = atomicAdd(&g_nfast, 1u);
                        if (fp < FASTCAP) g_fast[fp] = key;
                    }
                }
            }
        }
    }
}

// =================== K2: tail pipeline (16 blocks) ===================
__global__ void __launch_bounds__(512) k_tail(const float4* __restrict__ loc4,
                                              const float4* __restrict__ pri4,
                                              float* __restrict__ out) {
    int t = threadIdx.x;
    int b = blockIdx.x;                               // 0..15

    __shared__ float4 scand[KDET];
    __shared__ float  sa04[KDET];                     // 0.4f * area
    float4 bi; float sc;

    if (b == 15) {
        // ---------------- finish ----------------
        __shared__ unsigned long long skf[FASTCAP];   // fast keys (16KB)
        __shared__ unsigned long long sk2[CAND_CAP];  // top keys by rank (8KB)
        sk2[t] = 0ULL; sk2[t + 512] = 0ULL;

        unsigned nf = g_nfast;
        if (nf >= (unsigned)KDET && nf <= (unsigned)FASTCAP) {
            // ===== FAST PATH: coalesced load + full rank-sort =====
#pragma unroll
            for (int r = 0; r < 4; r++) {
                unsigned p = (unsigned)t + r * 512u;
                skf[p] = (p < nf) ? g_fast[p] : 0ULL;
            }
            __syncthreads();
#pragma unroll
            for (int r = 0; r < 4; r++) {
                unsigned p = (unsigned)t + r * 512u;
                unsigned long long key = skf[p];
                if (key) {
                    unsigned rank = 0;
                    for (unsigned k = 0; k < nf; k++)
                        rank += (skf[k] > key) ? 1u : 0u;   // broadcast LDS
                    if (rank < (unsigned)KDET) sk2[rank] = key;
                }
            }
            __syncthreads();
        } else {
            // ===== FALLBACK: hist suffix-scan -> cutoff -> gather -> sort ====
            __shared__ unsigned sB, wtot[16];
            __shared__ unsigned long long sk[CAND_CAP];
            __shared__ unsigned sinfo[CAND_CAP];
            if (t == 0) sB = 0u;
            sk[t] = 0ULL;  sk[t + 512] = 0ULL;
            sinfo[t] = 0u; sinfo[t + 512] = 0u;

            unsigned h[16];
            {
                const uint4* hv = (const uint4*)&g_hist[t * 16];
                uint4 a = hv[0], bb = hv[1], cc = hv[2], d = hv[3];
                h[0]=a.x; h[1]=a.y; h[2]=a.z; h[3]=a.w;
                h[4]=bb.x; h[5]=bb.y; h[6]=bb.z; h[7]=bb.w;
                h[8]=cc.x; h[9]=cc.y; h[10]=cc.z; h[11]=cc.w;
                h[12]=d.x; h[13]=d.y; h[14]=d.z; h[15]=d.w;
            }
            unsigned psum = 0;
#pragma unroll
            for (int j = 0; j < 16; j++) psum += h[j];

            unsigned s = psum;
            int lane = t & 31, wid = t >> 5;
#pragma unroll
            for (int off = 1; off < 32; off <<= 1) {
                unsigned v = __shfl_down_sync(0xFFFFFFFFu, s, off);
                if (lane + off < 32) s += v;
            }
            if (lane == 0) wtot[wid] = s;
            __syncthreads();
            unsigned tail = 0;
            for (int w2 = wid + 1; w2 < 16; w2++) tail += wtot[w2];
            unsigned suf_excl = s + tail - psum;

            {
                unsigned cum = suf_excl;
                int best = -1;
#pragma unroll
                for (int j = 15; j >= 0; j--) {
                    cum += h[j];
                    if (cum >= KDET) { best = t * 16 + j; break; }
                }
                if (best >= 0) atomicMax(&sB, (unsigned)best);
            }
            __syncthreads();
            unsigned B = sB;

            {
                unsigned suf = suf_excl;
#pragma unroll
                for (int j = 15; j >= 0; j--) {
                    unsigned bb = (unsigned)t * 16 + (unsigned)j;
                    if (bb >= B && h[j] > 0 && suf < CAND_CAP) {
                        unsigned cn = min(min(h[j], (unsigned)SLOTS),
                                          (unsigned)CAND_CAP - suf);
                        unsigned info = (suf << 16) | cn;
                        for (unsigned k = 0; k < cn; k++) {
                            sk[suf + k] = g_bins[bb * SLOTS + k];
                            sinfo[suf + k] = info;
                        }
                    }
                    suf += h[j];
                }
            }
            __syncthreads();

#pragma unroll
            for (int r = 0; r < 2; r++) {
                int p = t + r * 512;
                unsigned long long key = sk[p];
                if (key) {
                    unsigned info = sinfo[p];
                    unsigned bs = info >> 16, cn = info & 0xFFFFu;
                    unsigned rank2 = 0;
                    for (unsigned k = 0; k < cn; k++)
                        rank2 += (sk[bs + k] > key) ? 1u : 0u;
                    if (bs + rank2 < (unsigned)KDET) sk2[bs + rank2] = key;
                }
            }
            __syncthreads();
        }

        // decode top 512
        {
            unsigned long long key = sk2[t];
            unsigned sb = (unsigned)(key >> 32);
            float4 c = make_float4(0.f, 0.f, 0.f, 0.f);
            sc = 0.f;
            if (sb) {
                unsigned idx = 0xFFFFFFFFu - (unsigned)(key & 0xFFFFFFFFull);
                float4 l = loc4[idx];
                float4 p = pri4[idx];
                float cx = p.x + (l.x * 0.1f) * p.z;
                float cy = p.y + (l.y * 0.1f) * p.w;
                float w  = p.z * expf(l.z * 0.2f);
                float hh = p.w * expf(l.w * 0.2f);
                float x1 = cx - w * 0.5f;
                float y1 = cy - hh * 0.5f;
                float x2 = x1 + w;
                float y2 = y1 + hh;
                c = make_float4(x1 * 2048.f, y1 * 2048.f, x2 * 2048.f, y2 * 2048.f);
                sc = __uint_as_float(sb);
            }
            g_cand[t]  = c;
            g_score[t] = sc;
            bi = c;
            scand[t] = c;
            sa04[t]  = 0.4f * (c.z - c.x + 1.f) * (c.w - c.y + 1.f);
        }
        __threadfence();
        __syncthreads();
        if (t == 0) atomicExch(&g_flag, 1u);          // release decode
    } else {
        // spinner: wait for decode (all 16 blocks resident)
        if (t == 0) {
            while (atomicAdd(&g_flag, 0u) == 0u) __nanosleep(64);
        }
        __syncthreads();
        __threadfence();                              // acquire
        bi = g_cand[t];
        sc = g_score[t];
        scand[t] = bi;
        sa04[t]  = 0.4f * (bi.z - bi.x + 1.f) * (bi.w - bi.y + 1.f);
    }
    __syncthreads();

    // ---------------- mask chunk (division-free IoU) ----------------
    // iou>0.4 <=> 1.4*inter > 0.4*(areai+areaj)  (areas >= 1 so denom > 0)
    {
        float a04 = sa04[t];
        unsigned bits = 0u;
#pragma unroll 8
        for (int bb = 0; bb < 32; bb++) {
            int j = b * 32 + bb;
            float4 bj = scand[j];
            float xx1 = fmaxf(bi.x, bj.x), yy1 = fmaxf(bi.y, bj.y);
            float xx2 = fminf(bi.z, bj.z), yy2 = fminf(bi.w, bj.w);
            float ww = fmaxf(xx2 - xx1 + 1.f, 0.f);
            float hh = fmaxf(yy2 - yy1 + 1.f, 0.f);
            float inter = ww * hh;
            bool sgt = 1.4f * inter > a04 + sa04[j];
            if (sgt && j < t) bits |= (1u << bb);
        }
        g_sup[b * 512 + t] = bits;
    }

    // last-done election
    __shared__ unsigned s_last;
    __syncthreads();
    if (t == 0) {
        __threadfence();
        unsigned old = atomicAdd(&g_done2, 1u);
        s_last = (old == 15u) ? 1u : 0u;
    }
    __syncthreads();
    if (!s_last) return;
    __threadfence();

    // ---------------- forward word-sweep NMS (exact, 16 steps) -----------
    unsigned supw[16];
#pragma unroll
    for (int w = 0; w < 16; w++) supw[w] = g_sup[w * 512 + t];
    int wme = t >> 5, lane = t & 31;
    unsigned intra = g_sup[wme * 512 + t];
    bool k0 = sc > 0.0f;                              // keep0 = top_s > 0
    unsigned below = (1u << lane) - 1u;

    // restore scratch invariants for next replay
    {
        uint4* hz = (uint4*)g_hist;
#pragma unroll
        for (int i = 0; i < 4; i++)
            hz[t + i * 512] = make_uint4(0u, 0u, 0u, 0u);
    }

    __shared__ unsigned skeep[16];
    bool suppressed = false;
#pragma unroll
    for (int w = 0; w < 16; w++) {
        if (wme == w) {
            // intra-word greedy via word-local Jacobi (exact; terminates <=33
            // by strict lower-index dependency; consecutive-equal pins it)
            unsigned tent = __ballot_sync(0xFFFFFFFFu, k0 && !suppressed);
            unsigned fcur = tent, prev;
            do {
                prev = fcur;
                bool killed = (intra & fcur & below) != 0u;
                fcur = __ballot_sync(0xFFFFFFFFu, !killed) & tent;
            } while (fcur != prev);
            if (lane == 0) skeep[w] = fcur;
        }
        __syncthreads();
        suppressed = suppressed || ((supw[w] & skeep[w]) != 0u);
    }

    unsigned kept = (skeep[wme] >> lane) & 1u;
    const float inv = 1.0f / 2048.0f;                 // exact (power of 2)
    float o0 = 0.f, o1 = 0.f, o2 = 0.f, o3 = 0.f, o4 = 0.f;
    if (kept) { o0 = bi.x * inv; o1 = bi.y * inv; o2 = bi.z * inv; o3 = bi.w * inv; o4 = sc; }
    out[t * 5 + 0] = o0;
    out[t * 5 + 1] = o1;
    out[t * 5 + 2] = o2;
    out[t * 5 + 3] = o3;
    out[t * 5 + 4] = o4;

    if (t == 0) { g_flag = 0u; g_done2 = 0u; g_nfast = 0u; }
}

extern "C" void kernel_launch(void* const* d_in, const int* in_sizes, int n_in,
                              void* d_out, int out_size) {
    const float4* loc4  = (const float4*)d_in[0];
    const float4* conf4 = (const float4*)d_in[1];
    const float4* pri4  = (const float4*)d_in[2];
    float* out = (float*)d_out;

    int nElem  = in_sizes[1] / 2;                   // N priors
    int nPairs = (nElem + 1) / 2;                   // float4 count of conf
    int G = (nPairs + 512 * PF - 1) / (512 * PF);   // 512 blocks for N=2M

    k_scan<<<G, 512>>>(conf4, nPairs);
    k_tail<<<16, 512>>>(loc4, pri4, out);
}